// round 11
// baseline (speedup 1.0000x reference)
#include <cuda_runtime.h>
#include <cstdint>

#define NN  100000
#define EE  1600000
#define HD  128
#define BB  4096
#define NCTX 20

#define TILE_M 64
#define NTILES ((NN + TILE_M - 1) / TILE_M)   // 1563
#define HSTR 132
#define WSTR 132
#define SMEM_DYN ((TILE_M * HSTR + HD * WSTR) * 4)   // 101376 B -> 2 blocks/SM

// ---------------- scratch ----------------
__device__ int    g_deg[NN];
__device__ int    g_off[NN + 1];
__device__ int    g_cur[NN];
__device__ int2   g_csr_e[EE];          // (src, w bits)
__device__ short4 g_qA[NN * 32];        // int16-quantized ndata (4 vals/short4)
__device__ short4 g_qB[NN * 32];        // int16-quantized x1
__device__ float  g_sA[NN];             // row scales for g_qA
__device__ float  g_sB[NN];             // row scales for g_qB
__device__ float  g_x2[NN * HD];
__device__ float  g_WcT1[384 * 128];
__device__ float  g_WcT2[128 * 64];
__device__ int    g_part[256];
__device__ int    g_idx_is64;

// ---------------- helpers ----------------
__device__ __forceinline__ uint32_t f2tf32(float v) {
    uint32_t r;
    asm("cvt.rna.tf32.f32 %0, %1;" : "=r"(r) : "f"(v));
    return r;
}
// d += A(16x8 tf32) * B(8x8 tf32), fp32 accum, in-place
__device__ __forceinline__ void mma8(float* d, const uint32_t* a, uint32_t b0, uint32_t b1) {
    asm volatile(
        "mma.sync.aligned.m16n8k8.row.col.f32.tf32.tf32.f32 "
        "{%0,%1,%2,%3}, {%4,%5,%6,%7}, {%8,%9}, {%0,%1,%2,%3};\n"
        : "+f"(d[0]), "+f"(d[1]), "+f"(d[2]), "+f"(d[3])
        : "r"(a[0]), "r"(a[1]), "r"(a[2]), "r"(a[3]), "r"(b0), "r"(b1));
}

// ---------------- prep: zero + detect + Wc transposes ----------------
__global__ void k_prep(const void* __restrict__ idx,
                       const float* __restrict__ Wc1, const float* __restrict__ Wc2)
{
    int b = blockIdx.x, t = threadIdx.x;
    if (b < 391) {
        int i = b * 256 + t;
        if (i < NN) { g_deg[i] = 0; g_cur[i] = 0; }
    } else if (b == 391) {
        if (t == 0) {
            const long long* p = (const long long*)idx;
            int ok = 1;
            for (int i = 0; i < 23; ++i) { long long v = p[i]; if (v < 0 || v >= NN) ok = 0; }
            g_idx_is64 = ok;
        }
    } else if (b < 584) {               // WcT1: 49152 elems
        int e = (b - 392) * 256 + t;
        int j = e / 384, k = e - j * 384;
        g_WcT1[k * 128 + j] = Wc1[e];
    } else {                            // WcT2: 8192 elems
        int e = (b - 584) * 256 + t;
        int j = e >> 7, k = e & 127;
        g_WcT2[k * 64 + j] = Wc2[e];
    }
}

// ---------------- quantize ndata -> g_qA/g_sA (warp per row) ----------------
__global__ __launch_bounds__(256) void k_quant(const float* __restrict__ x) {
    int row = blockIdx.x * 8 + (threadIdx.x >> 5);
    int lane = threadIdx.x & 31;
    if (row >= NN) return;
    float4 v = ((const float4*)x)[row * 32 + lane];
    float m = fmaxf(fmaxf(fabsf(v.x), fabsf(v.y)), fmaxf(fabsf(v.z), fabsf(v.w)));
    #pragma unroll
    for (int o = 16; o > 0; o >>= 1) m = fmaxf(m, __shfl_xor_sync(0xffffffffu, m, o));
    float qs = (m > 0.f) ? 32766.f / m : 0.f;
    short4 q;
    q.x = (short)rintf(v.x * qs);
    q.y = (short)rintf(v.y * qs);
    q.z = (short)rintf(v.z * qs);
    q.w = (short)rintf(v.w * qs);
    g_qA[row * 32 + lane] = q;
    if (lane == 0) g_sA[row] = m * (1.f / 32766.f);
}

// ---------------- CSR build ----------------
__global__ void k_deg(const int* __restrict__ dst) {
    int e = blockIdx.x * 256 + threadIdx.x;
    if (e < EE) {
        int d = min(max(dst[e], 0), NN - 1);
        atomicAdd(&g_deg[d], 1);
    }
}

__global__ void k_scan1() {
    __shared__ int s[512];
    int tid = threadIdx.x;
    int gid = blockIdx.x * 512 + tid;
    int v = (gid < NN) ? g_deg[gid] : 0;
    s[tid] = v; __syncthreads();
    for (int o = 1; o < 512; o <<= 1) {
        int t = (tid >= o) ? s[tid - o] : 0;
        __syncthreads();
        s[tid] += t;
        __syncthreads();
    }
    if (gid < NN) g_off[gid] = s[tid] - v;
    if (tid == 511) g_part[blockIdx.x] = s[511];
}

__global__ void k_scan3() {
    __shared__ int red[16];
    __shared__ int sOff;
    int b = blockIdx.x, tid = threadIdx.x;
    int acc = 0;
    for (int i = tid; i < b; i += 512) acc += g_part[i];
    #pragma unroll
    for (int o = 16; o > 0; o >>= 1) acc += __shfl_down_sync(0xffffffffu, acc, o);
    if ((tid & 31) == 0) red[tid >> 5] = acc;
    __syncthreads();
    if (tid == 0) {
        int s = 0;
        #pragma unroll
        for (int i = 0; i < 16; ++i) s += red[i];
        sOff = s;
    }
    __syncthreads();
    int gid = b * 512 + tid;
    if (gid < NN) g_off[gid] += sOff;
    if (b == 0 && tid == 0) g_off[NN] = EE;
}

__global__ void k_csr(const int* __restrict__ src, const int* __restrict__ dst,
                      const float* __restrict__ w) {
    int e = blockIdx.x * 256 + threadIdx.x;
    if (e < EE) {
        int d = min(max(dst[e], 0), NN - 1);
        int s = min(max(src[e], 0), NN - 1);
        int slot = g_off[d] + atomicAdd(&g_cur[d], 1);
        g_csr_e[slot] = make_int2(s, __float_as_int(w[e]));
    }
}

// ---------------- fused GIN layer: int16 gather -> tf32 mma.sync (3xTF32) -> epilogue ----------------
// 64 nodes/block, 8 warps = 2(m) x 4(n). layer 0: quantize output to g_qB. layer 1: fp32 to g_x2.
__global__ __launch_bounds__(256, 2)
void k_layer(const float* __restrict__ b,
             const float* __restrict__ W,
             const float* __restrict__ eps,
             int layer)
{
    extern __shared__ float smem[];
    float* Hs = smem;                        // [64][HSTR]
    float* Ws = smem + TILE_M * HSTR;        // [128][WSTR]
    __shared__ float bs[128];

    const short4* qin = layer ? g_qB : g_qA;
    const float*  sin = layer ? g_sB : g_sA;

    int tid = threadIdx.x, warp = tid >> 5, lane = tid & 31;
    int nodeBase = blockIdx.x * TILE_M;
    float epsv = 1.0f + __ldg(&eps[layer]);

    if (tid < 128) bs[tid] = b[tid];

    // copy W (64KB) into padded smem
    {
        const float4* wsrc = (const float4*)W;
        #pragma unroll
        for (int i = 0; i < 16; ++i) {
            int idx = tid + i * 256;
            int r = idx >> 5, s = idx & 31;
            *(float4*)&Ws[r * WSTR + (s << 2)] = __ldg(&wsrc[idx]);
        }
    }

    // gather: each warp computes h for 8 nodes from int16-quantized features
    for (int n = 0; n < 8; ++n) {
        int m = warp * 8 + n;
        int node = nodeBase + m;
        int beg = 0, end = 0;
        if (node < NN) { beg = g_off[node]; end = g_off[node + 1]; }
        float ax = 0.f, ay = 0.f, az = 0.f, aw = 0.f;
        for (int base = beg; base < end; base += 32) {
            int nrem = end - base; if (nrem > 32) nrem = 32;
            int sIdx = 0; float wls = 0.f;
            if (lane < nrem) {
                int2 ed = g_csr_e[base + lane];
                sIdx = ed.x;
                wls  = __int_as_float(ed.y) * __ldg(&sin[ed.x]);
            }
            #pragma unroll 8
            for (int j = 0; j < nrem; ++j) {
                int   ss = __shfl_sync(0xffffffffu, sIdx, j);
                float ws = __shfl_sync(0xffffffffu, wls, j);
                short4 qv = qin[ss * 32 + lane];
                ax += ws * (float)qv.x;
                ay += ws * (float)qv.y;
                az += ws * (float)qv.z;
                aw += ws * (float)qv.w;
            }
        }
        float4 h = make_float4(0.f, 0.f, 0.f, 0.f);
        if (node < NN) {
            float inv = 1.0f / fmaxf((float)(end - beg), 1.0f);
            short4 qv = qin[node * 32 + lane];
            float  sv = sin[node] * epsv;
            h.x = sv * (float)qv.x + ax * inv;
            h.y = sv * (float)qv.y + ay * inv;
            h.z = sv * (float)qv.z + az * inv;
            h.w = sv * (float)qv.w + aw * inv;
        }
        *(float4*)&Hs[m * HSTR + (lane << 2)] = h;
    }
    __syncthreads();

    // GEMM: Out[64][128] = H[64][128] @ W^T, 3xTF32 via mma.sync
    int wm = warp >> 2;
    int wn = warp & 3;
    int g  = lane >> 2, t = lane & 3;

    float acc[2][4][4];
    #pragma unroll
    for (int mt = 0; mt < 2; ++mt)
        #pragma unroll
        for (int nt = 0; nt < 4; ++nt)
            #pragma unroll
            for (int i = 0; i < 4; ++i) acc[mt][nt][i] = 0.f;

    #pragma unroll 2
    for (int kt = 0; kt < 16; ++kt) {
        int k0 = kt * 8;
        uint32_t ah[2][4], al[2][4];
        #pragma unroll
        for (int mt = 0; mt < 2; ++mt) {
            int row = wm * 32 + mt * 16 + g;
            float v0 = Hs[row * HSTR + k0 + t];
            float v1 = Hs[(row + 8) * HSTR + k0 + t];
            float v2 = Hs[row * HSTR + k0 + t + 4];
            float v3 = Hs[(row + 8) * HSTR + k0 + t + 4];
            ah[mt][0] = f2tf32(v0); al[mt][0] = f2tf32(v0 - __uint_as_float(ah[mt][0]));
            ah[mt][1] = f2tf32(v1); al[mt][1] = f2tf32(v1 - __uint_as_float(ah[mt][1]));
            ah[mt][2] = f2tf32(v2); al[mt][2] = f2tf32(v2 - __uint_as_float(ah[mt][2]));
            ah[mt][3] = f2tf32(v3); al[mt][3] = f2tf32(v3 - __uint_as_float(ah[mt][3]));
        }
        #pragma unroll
        for (int nt = 0; nt < 4; ++nt) {
            int nj = wn * 32 + nt * 8 + g;
            float bv0 = Ws[nj * WSTR + k0 + t];
            float bv1 = Ws[nj * WSTR + k0 + t + 4];
            uint32_t bh0 = f2tf32(bv0), bh1 = f2tf32(bv1);
            uint32_t bl0 = f2tf32(bv0 - __uint_as_float(bh0));
            uint32_t bl1 = f2tf32(bv1 - __uint_as_float(bh1));
            #pragma unroll
            for (int mt = 0; mt < 2; ++mt) {
                mma8(acc[mt][nt], ah[mt], bh0, bh1);
                mma8(acc[mt][nt], al[mt], bh0, bh1);
                mma8(acc[mt][nt], ah[mt], bl0, bl1);
            }
        }
    }

    if (layer == 0) {
        // epilogue A: bias + relu -> Hs -> quantize rows to g_qB / g_sB
        __syncthreads();     // all warps done reading Hs/Ws
        #pragma unroll
        for (int mt = 0; mt < 2; ++mt) {
            int lm = wm * 32 + mt * 16 + g;
            #pragma unroll
            for (int nt = 0; nt < 4; ++nt) {
                int col = wn * 32 + nt * 8 + (t << 1);
                float b0 = bs[col], b1 = bs[col + 1];
                float v00 = fmaxf(acc[mt][nt][0] + b0, 0.f);
                float v01 = fmaxf(acc[mt][nt][1] + b1, 0.f);
                float v10 = fmaxf(acc[mt][nt][2] + b0, 0.f);
                float v11 = fmaxf(acc[mt][nt][3] + b1, 0.f);
                *(float2*)&Hs[lm * HSTR + col]       = make_float2(v00, v01);
                *(float2*)&Hs[(lm + 8) * HSTR + col] = make_float2(v10, v11);
            }
        }
        __syncthreads();
        #pragma unroll
        for (int r = 0; r < 8; ++r) {
            int lm = warp * 8 + r;
            int node = nodeBase + lm;
            if (node < NN) {
                float4 v = *(float4*)&Hs[lm * HSTR + (lane << 2)];
                float m = fmaxf(fmaxf(fabsf(v.x), fabsf(v.y)), fmaxf(fabsf(v.z), fabsf(v.w)));
                #pragma unroll
                for (int o = 16; o > 0; o >>= 1) m = fmaxf(m, __shfl_xor_sync(0xffffffffu, m, o));
                float qs = (m > 0.f) ? 32766.f / m : 0.f;
                short4 q;
                q.x = (short)rintf(v.x * qs);
                q.y = (short)rintf(v.y * qs);
                q.z = (short)rintf(v.z * qs);
                q.w = (short)rintf(v.w * qs);
                g_qB[node * 32 + lane] = q;
                if (lane == 0) g_sB[node] = m * (1.f / 32766.f);
            }
        }
    } else {
        // epilogue B: bias (+ node0 zero) -> fp32 g_x2
        #pragma unroll
        for (int mt = 0; mt < 2; ++mt) {
            int node0 = nodeBase + wm * 32 + mt * 16 + g;
            #pragma unroll
            for (int nt = 0; nt < 4; ++nt) {
                int col = wn * 32 + nt * 8 + (t << 1);
                float b0 = bs[col], b1 = bs[col + 1];
                float v00 = acc[mt][nt][0] + b0, v01 = acc[mt][nt][1] + b1;
                float v10 = acc[mt][nt][2] + b0, v11 = acc[mt][nt][3] + b1;
                if (node0 == 0) { v00 = 0.f; v01 = 0.f; }
                if (node0 < NN)     *(float2*)(g_x2 + node0 * 128 + col)       = make_float2(v00, v01);
                if (node0 + 8 < NN) *(float2*)(g_x2 + (node0 + 8) * 128 + col) = make_float2(v10, v11);
            }
        }
    }
}

// ---------------- head MLP: 8 rows per block, dual-dtype index gather ----------------
__global__ __launch_bounds__(256) void k_head(const void* __restrict__ idxp,
                                              const float* __restrict__ bc1,
                                              const float* __restrict__ bc2,
                                              const float* __restrict__ wc3,
                                              const float* __restrict__ bc3,
                                              float* __restrict__ out)
{
    __shared__ float fs [8][384];
    __shared__ float y1s[8][128];
    __shared__ float y2s[8][64];
    int tid = threadIdx.x, warp = tid >> 5, lane = tid & 31;
    int rowBase = blockIdx.x << 3;

    {
        int row = rowBase + warp;
        int i1, i2, cnt = 0;
        int ctxi[NCTX];
        if (g_idx_is64) {
            const long long* ip = (const long long*)idxp + (long long)row * 23;
            i1 = (int)ip[0]; i2 = (int)ip[1];
            #pragma unroll
            for (int t = 0; t < NCTX; ++t) {
                long long cl = ip[3 + t];
                ctxi[t] = min(max((int)cl, 0), NN - 1);
                if (cl > 0) cnt++;
            }
        } else {
            const int* ip = (const int*)idxp + row * 23;
            i1 = ip[0]; i2 = ip[1];
            #pragma unroll
            for (int t = 0; t < NCTX; ++t) {
                int ci = ip[3 + t];
                ctxi[t] = min(max(ci, 0), NN - 1);
                if (ci > 0) cnt++;
            }
        }
        i1 = min(max(i1, 0), NN - 1);
        i2 = min(max(i2, 0), NN - 1);

        const float4* x4 = (const float4*)g_x2;
        *(float4*)&fs[warp][lane << 2]         = x4[i1 * 32 + lane];
        *(float4*)&fs[warp][128 + (lane << 2)] = x4[i2 * 32 + lane];
        float sx = 0.f, sy = 0.f, sz = 0.f, sw = 0.f;
        #pragma unroll 4
        for (int t = 0; t < NCTX; ++t) {
            float4 xv = x4[ctxi[t] * 32 + lane];
            sx += xv.x; sy += xv.y; sz += xv.z; sw += xv.w;
        }
        float inv = 1.0f / (float)(cnt > 0 ? cnt : 1);
        float4 cv; cv.x = sx * inv; cv.y = sy * inv; cv.z = sz * inv; cv.w = sw * inv;
        *(float4*)&fs[warp][256 + (lane << 2)] = cv;
    }
    __syncthreads();

    {
        int j  = tid & 127;
        int r0 = (tid >> 7) << 2;
        float a0 = bc1[j], a1 = a0, a2 = a0, a3 = a0;
        #pragma unroll 4
        for (int k = 0; k < 384; ++k) {
            float wv = g_WcT1[k * 128 + j];
            a0 += fs[r0 + 0][k] * wv;
            a1 += fs[r0 + 1][k] * wv;
            a2 += fs[r0 + 2][k] * wv;
            a3 += fs[r0 + 3][k] * wv;
        }
        y1s[r0 + 0][j] = fmaxf(a0, 0.f);
        y1s[r0 + 1][j] = fmaxf(a1, 0.f);
        y1s[r0 + 2][j] = fmaxf(a2, 0.f);
        y1s[r0 + 3][j] = fmaxf(a3, 0.f);
    }
    __syncthreads();

    {
        int j  = tid & 63;
        int r0 = (tid >> 6) << 1;
        float a0 = bc2[j], a1 = a0;
        #pragma unroll 4
        for (int k = 0; k < 128; ++k) {
            float wv = g_WcT2[k * 64 + j];
            a0 += y1s[r0 + 0][k] * wv;
            a1 += y1s[r0 + 1][k] * wv;
        }
        y2s[r0 + 0][j] = fmaxf(a0, 0.f);
        y2s[r0 + 1][j] = fmaxf(a1, 0.f);
    }
    __syncthreads();

    {
        float p = y2s[warp][lane] * wc3[lane] + y2s[warp][lane + 32] * wc3[lane + 32];
        #pragma unroll
        for (int o = 16; o > 0; o >>= 1) p += __shfl_down_sync(0xffffffffu, p, o);
        if (lane == 0) out[rowBase + warp] = p + bc3[0];
    }
}

// ---------------- launch ----------------
extern "C" void kernel_launch(void* const* d_in, const int* in_sizes, int n_in,
                              void* d_out, int out_size)
{
    const void*  indices = d_in[0];
    const int*   src   = (const int*)  d_in[1];
    const int*   dst   = (const int*)  d_in[2];
    const float* w     = (const float*)d_in[3];
    const float* ndata = (const float*)d_in[4];
    const float* W1    = (const float*)d_in[5];
    const float* b1    = (const float*)d_in[6];
    const float* W2    = (const float*)d_in[7];
    const float* b2    = (const float*)d_in[8];
    const float* eps   = (const float*)d_in[9];
    const float* Wc1   = (const float*)d_in[10];
    const float* bc1   = (const float*)d_in[11];
    const float* Wc2   = (const float*)d_in[12];
    const float* bc2   = (const float*)d_in[13];
    const float* Wc3   = (const float*)d_in[14];
    const float* bc3   = (const float*)d_in[15];
    float* out = (float*)d_out;

    (void)in_sizes; (void)n_in; (void)out_size;

    static bool s_attr = false;
    if (!s_attr) {
        cudaFuncSetAttribute(k_layer, cudaFuncAttributeMaxDynamicSharedMemorySize, SMEM_DYN);
        s_attr = true;
    }

    int nbScan = (NN + 511) / 512;

    k_prep <<<616, 256>>>(indices, Wc1, Wc2);
    k_quant<<<(NN + 7) / 8, 256>>>(ndata);
    k_deg  <<<(EE + 255) / 256, 256>>>(dst);
    k_scan1<<<nbScan, 512>>>();
    k_scan3<<<nbScan, 512>>>();
    k_csr  <<<(EE + 255) / 256, 256>>>(src, dst, w);

    k_layer<<<NTILES, 256, SMEM_DYN>>>(b1, W1, eps, 0);
    k_layer<<<NTILES, 256, SMEM_DYN>>>(b2, W2, eps, 1);

    k_head <<<BB / 8, 256>>>(indices, bc1, bc2, Wc3, bc3, out);
}

// round 16
// speedup vs baseline: 1.4272x; 1.4272x over previous
#include <cuda_runtime.h>
#include <cstdint>

#define NN  100000
#define EE  1600000
#define HD  128
#define BB  4096
#define NCTX 20

#define TILE_M 64
#define NTILES ((NN + TILE_M - 1) / TILE_M)   // 1563
#define HSTR 132
#define WSTR 132
#define SMEM_DYN ((TILE_M * HSTR + HD * WSTR) * 4)   // 101376 B -> 2 blocks/SM for k_gemm

// ---------------- scratch ----------------
__device__ int    g_deg[NN];
__device__ int    g_off[NN + 1];
__device__ int    g_cur[NN];
__device__ int2   g_csr_e[EE];          // (src, w bits)
__device__ float  g_h [NN * HD];        // gather output (GEMM input)
__device__ float  g_x1[NN * HD];
__device__ float  g_x2[NN * HD];
__device__ float  g_WcT1[384 * 128];
__device__ float  g_WcT2[128 * 64];
__device__ int    g_part[256];
__device__ int    g_idx_is64;

// ---------------- helpers ----------------
__device__ __forceinline__ uint32_t f2tf32(float v) {
    uint32_t r;
    asm("cvt.rna.tf32.f32 %0, %1;" : "=r"(r) : "f"(v));
    return r;
}
__device__ __forceinline__ void mma8(float* d, const uint32_t* a, uint32_t b0, uint32_t b1) {
    asm volatile(
        "mma.sync.aligned.m16n8k8.row.col.f32.tf32.tf32.f32 "
        "{%0,%1,%2,%3}, {%4,%5,%6,%7}, {%8,%9}, {%0,%1,%2,%3};\n"
        : "+f"(d[0]), "+f"(d[1]), "+f"(d[2]), "+f"(d[3])
        : "r"(a[0]), "r"(a[1]), "r"(a[2]), "r"(a[3]), "r"(b0), "r"(b1));
}

// ---------------- prep: zero + detect + Wc transposes ----------------
__global__ void k_prep(const void* __restrict__ idx,
                       const float* __restrict__ Wc1, const float* __restrict__ Wc2)
{
    int b = blockIdx.x, t = threadIdx.x;
    if (b < 391) {
        int i = b * 256 + t;
        if (i < NN) { g_deg[i] = 0; g_cur[i] = 0; }
    } else if (b == 391) {
        if (t == 0) {
            const long long* p = (const long long*)idx;
            int ok = 1;
            for (int i = 0; i < 23; ++i) { long long v = p[i]; if (v < 0 || v >= NN) ok = 0; }
            g_idx_is64 = ok;
        }
    } else if (b < 584) {               // WcT1: 49152 elems
        int e = (b - 392) * 256 + t;
        int j = e / 384, k = e - j * 384;
        g_WcT1[k * 128 + j] = Wc1[e];
    } else {                            // WcT2: 8192 elems
        int e = (b - 584) * 256 + t;
        int j = e >> 7, k = e & 127;
        g_WcT2[k * 64 + j] = Wc2[e];
    }
}

// ---------------- CSR build ----------------
__global__ void k_deg(const int* __restrict__ dst) {
    int e = blockIdx.x * 256 + threadIdx.x;
    if (e < EE) {
        int d = min(max(dst[e], 0), NN - 1);
        atomicAdd(&g_deg[d], 1);
    }
}

__global__ void k_scan1() {
    __shared__ int s[512];
    int tid = threadIdx.x;
    int gid = blockIdx.x * 512 + tid;
    int v = (gid < NN) ? g_deg[gid] : 0;
    s[tid] = v; __syncthreads();
    for (int o = 1; o < 512; o <<= 1) {
        int t = (tid >= o) ? s[tid - o] : 0;
        __syncthreads();
        s[tid] += t;
        __syncthreads();
    }
    if (gid < NN) g_off[gid] = s[tid] - v;
    if (tid == 511) g_part[blockIdx.x] = s[511];
}

__global__ void k_scan3() {
    __shared__ int red[16];
    __shared__ int sOff;
    int b = blockIdx.x, tid = threadIdx.x;
    int acc = 0;
    for (int i = tid; i < b; i += 512) acc += g_part[i];
    #pragma unroll
    for (int o = 16; o > 0; o >>= 1) acc += __shfl_down_sync(0xffffffffu, acc, o);
    if ((tid & 31) == 0) red[tid >> 5] = acc;
    __syncthreads();
    if (tid == 0) {
        int s = 0;
        #pragma unroll
        for (int i = 0; i < 16; ++i) s += red[i];
        sOff = s;
    }
    __syncthreads();
    int gid = b * 512 + tid;
    if (gid < NN) g_off[gid] += sOff;
    if (b == 0 && tid == 0) g_off[NN] = EE;
}

__global__ void k_csr(const int* __restrict__ src, const int* __restrict__ dst,
                      const float* __restrict__ w) {
    int e = blockIdx.x * 256 + threadIdx.x;
    if (e < EE) {
        int d = min(max(dst[e], 0), NN - 1);
        int s = min(max(src[e], 0), NN - 1);
        int slot = g_off[d] + atomicAdd(&g_cur[d], 1);
        g_csr_e[slot] = make_int2(s, __float_as_int(w[e]));
    }
}

// ---------------- gather: warp per node, high occupancy, fp32 ----------------
// h[node] = (1+eps)*x[node] + (sum_e w_e * x[src_e]) / deg
// NOTE: input pointer selected INSIDE the kernel (device-symbol addresses are
// invalid as host-passed args; ATS makes that a silent-garbage read, not a fault).
__global__ __launch_bounds__(256) void k_gather(const float* __restrict__ ndata,
                                                const float* __restrict__ eps,
                                                int layer)
{
    int gw   = (blockIdx.x * 256 + threadIdx.x) >> 5;   // global warp id = node
    int lane = threadIdx.x & 31;
    if (gw >= NN) return;
    int node = gw;

    const float* xin = layer ? g_x1 : ndata;

    float epsv = 1.0f + __ldg(&eps[layer]);
    int beg = __ldg(&g_off[node]);
    int end = __ldg(&g_off[node + 1]);

    const float4* x4 = (const float4*)xin;
    float ax = 0.f, ay = 0.f, az = 0.f, aw = 0.f;

    for (int base = beg; base < end; base += 32) {
        int nrem = end - base; if (nrem > 32) nrem = 32;
        int2 ed = make_int2(0, 0);
        if (lane < nrem) ed = __ldg(&g_csr_e[base + lane]);
        #pragma unroll 8
        for (int j = 0; j < nrem; ++j) {
            int   ss = __shfl_sync(0xffffffffu, ed.x, j);
            float ww = __int_as_float(__shfl_sync(0xffffffffu, ed.y, j));
            float4 xv = x4[ss * 32 + lane];
            ax += ww * xv.x; ay += ww * xv.y; az += ww * xv.z; aw += ww * xv.w;
        }
    }

    float inv = 1.0f / fmaxf((float)(end - beg), 1.0f);
    float4 xi = x4[node * 32 + lane];
    float4 h;
    h.x = epsv * xi.x + ax * inv;
    h.y = epsv * xi.y + ay * inv;
    h.z = epsv * xi.z + az * inv;
    h.w = epsv * xi.w + aw * inv;
    ((float4*)g_h)[node * 32 + lane] = h;
}

// ---------------- GEMM: Out[64][128] = H[64][128] @ W^T, 3xTF32 mma.sync ----------------
// 8 warps = 2(m) x 4(n). layer 0: relu -> g_x1. layer 1: zero node0 -> g_x2.
__global__ __launch_bounds__(256, 2)
void k_gemm(const float* __restrict__ W,
            const float* __restrict__ b,
            int layer)
{
    extern __shared__ float smem[];
    float* Hs = smem;                        // [64][HSTR]
    float* Ws = smem + TILE_M * HSTR;        // [128][WSTR]
    __shared__ float bs[128];

    float* xout = layer ? g_x2 : g_x1;

    int tid = threadIdx.x, warp = tid >> 5, lane = tid & 31;
    int nodeBase = blockIdx.x * TILE_M;

    if (tid < 128) bs[tid] = b[tid];

    // stage W (64KB) and H tile (32KB) into padded smem
    {
        const float4* wsrc = (const float4*)W;
        #pragma unroll
        for (int i = 0; i < 16; ++i) {
            int idx = tid + i * 256;
            int r = idx >> 5, s = idx & 31;
            *(float4*)&Ws[r * WSTR + (s << 2)] = __ldg(&wsrc[idx]);
        }
        const float4* hsrc = (const float4*)g_h;
        #pragma unroll
        for (int i = 0; i < 8; ++i) {
            int idx = tid + i * 256;            // 0..2047
            int r = idx >> 5, s = idx & 31;
            int node = nodeBase + r;
            float4 v = (node < NN) ? hsrc[node * 32 + s] : make_float4(0.f, 0.f, 0.f, 0.f);
            *(float4*)&Hs[r * HSTR + (s << 2)] = v;
        }
    }
    __syncthreads();

    int wm = warp >> 2;
    int wn = warp & 3;
    int g  = lane >> 2, t = lane & 3;

    float acc[2][4][4];
    #pragma unroll
    for (int mt = 0; mt < 2; ++mt)
        #pragma unroll
        for (int nt = 0; nt < 4; ++nt)
            #pragma unroll
            for (int i = 0; i < 4; ++i) acc[mt][nt][i] = 0.f;

    #pragma unroll 2
    for (int kt = 0; kt < 16; ++kt) {
        int k0 = kt * 8;
        uint32_t ah[2][4], al[2][4];
        #pragma unroll
        for (int mt = 0; mt < 2; ++mt) {
            int row = wm * 32 + mt * 16 + g;
            float v0 = Hs[row * HSTR + k0 + t];
            float v1 = Hs[(row + 8) * HSTR + k0 + t];
            float v2 = Hs[row * HSTR + k0 + t + 4];
            float v3 = Hs[(row + 8) * HSTR + k0 + t + 4];
            ah[mt][0] = f2tf32(v0); al[mt][0] = f2tf32(v0 - __uint_as_float(ah[mt][0]));
            ah[mt][1] = f2tf32(v1); al[mt][1] = f2tf32(v1 - __uint_as_float(ah[mt][1]));
            ah[mt][2] = f2tf32(v2); al[mt][2] = f2tf32(v2 - __uint_as_float(ah[mt][2]));
            ah[mt][3] = f2tf32(v3); al[mt][3] = f2tf32(v3 - __uint_as_float(ah[mt][3]));
        }
        #pragma unroll
        for (int nt = 0; nt < 4; ++nt) {
            int nj = wn * 32 + nt * 8 + g;
            float bv0 = Ws[nj * WSTR + k0 + t];
            float bv1 = Ws[nj * WSTR + k0 + t + 4];
            uint32_t bh0 = f2tf32(bv0), bh1 = f2tf32(bv1);
            uint32_t bl0 = f2tf32(bv0 - __uint_as_float(bh0));
            uint32_t bl1 = f2tf32(bv1 - __uint_as_float(bh1));
            #pragma unroll
            for (int mt = 0; mt < 2; ++mt) {
                mma8(acc[mt][nt], ah[mt], bh0, bh1);
                mma8(acc[mt][nt], al[mt], bh0, bh1);
                mma8(acc[mt][nt], ah[mt], bl0, bl1);
            }
        }
    }

    // epilogue: bias + activation + store
    #pragma unroll
    for (int mt = 0; mt < 2; ++mt) {
        int node0 = nodeBase + wm * 32 + mt * 16 + g;
        #pragma unroll
        for (int nt = 0; nt < 4; ++nt) {
            int col = wn * 32 + nt * 8 + (t << 1);
            float b0 = bs[col], b1 = bs[col + 1];
            float v00 = acc[mt][nt][0] + b0, v01 = acc[mt][nt][1] + b1;
            float v10 = acc[mt][nt][2] + b0, v11 = acc[mt][nt][3] + b1;
            if (layer == 0) {
                v00 = fmaxf(v00, 0.f); v01 = fmaxf(v01, 0.f);
                v10 = fmaxf(v10, 0.f); v11 = fmaxf(v11, 0.f);
            } else if (node0 == 0) {
                v00 = 0.f; v01 = 0.f;
            }
            if (node0 < NN)     *(float2*)(xout + node0 * 128 + col)       = make_float2(v00, v01);
            if (node0 + 8 < NN) *(float2*)(xout + (node0 + 8) * 128 + col) = make_float2(v10, v11);
        }
    }
}

// ---------------- head MLP: 8 rows per block, dual-dtype index gather ----------------
__global__ __launch_bounds__(256) void k_head(const void* __restrict__ idxp,
                                              const float* __restrict__ bc1,
                                              const float* __restrict__ bc2,
                                              const float* __restrict__ wc3,
                                              const float* __restrict__ bc3,
                                              float* __restrict__ out)
{
    __shared__ float fs [8][384];
    __shared__ float y1s[8][128];
    __shared__ float y2s[8][64];
    int tid = threadIdx.x, warp = tid >> 5, lane = tid & 31;
    int rowBase = blockIdx.x << 3;

    {
        int row = rowBase + warp;
        int i1, i2, cnt = 0;
        int ctxi[NCTX];
        if (g_idx_is64) {
            const long long* ip = (const long long*)idxp + (long long)row * 23;
            i1 = (int)ip[0]; i2 = (int)ip[1];
            #pragma unroll
            for (int t = 0; t < NCTX; ++t) {
                long long cl = ip[3 + t];
                ctxi[t] = min(max((int)cl, 0), NN - 1);
                if (cl > 0) cnt++;
            }
        } else {
            const int* ip = (const int*)idxp + row * 23;
            i1 = ip[0]; i2 = ip[1];
            #pragma unroll
            for (int t = 0; t < NCTX; ++t) {
                int ci = ip[3 + t];
                ctxi[t] = min(max(ci, 0), NN - 1);
                if (ci > 0) cnt++;
            }
        }
        i1 = min(max(i1, 0), NN - 1);
        i2 = min(max(i2, 0), NN - 1);

        const float4* x4 = (const float4*)g_x2;
        *(float4*)&fs[warp][lane << 2]         = x4[i1 * 32 + lane];
        *(float4*)&fs[warp][128 + (lane << 2)] = x4[i2 * 32 + lane];
        float sx = 0.f, sy = 0.f, sz = 0.f, sw = 0.f;
        #pragma unroll 4
        for (int t = 0; t < NCTX; ++t) {
            float4 xv = x4[ctxi[t] * 32 + lane];
            sx += xv.x; sy += xv.y; sz += xv.z; sw += xv.w;
        }
        float inv = 1.0f / (float)(cnt > 0 ? cnt : 1);
        float4 cv; cv.x = sx * inv; cv.y = sy * inv; cv.z = sz * inv; cv.w = sw * inv;
        *(float4*)&fs[warp][256 + (lane << 2)] = cv;
    }
    __syncthreads();

    {
        int j  = tid & 127;
        int r0 = (tid >> 7) << 2;
        float a0 = bc1[j], a1 = a0, a2 = a0, a3 = a0;
        #pragma unroll 4
        for (int k = 0; k < 384; ++k) {
            float wv = g_WcT1[k * 128 + j];
            a0 += fs[r0 + 0][k] * wv;
            a1 += fs[r0 + 1][k] * wv;
            a2 += fs[r0 + 2][k] * wv;
            a3 += fs[r0 + 3][k] * wv;
        }
        y1s[r0 + 0][j] = fmaxf(a0, 0.f);
        y1s[r0 + 1][j] = fmaxf(a1, 0.f);
        y1s[r0 + 2][j] = fmaxf(a2, 0.f);
        y1s[r0 + 3][j] = fmaxf(a3, 0.f);
    }
    __syncthreads();

    {
        int j  = tid & 63;
        int r0 = (tid >> 6) << 1;
        float a0 = bc2[j], a1 = a0;
        #pragma unroll 4
        for (int k = 0; k < 128; ++k) {
            float wv = g_WcT2[k * 64 + j];
            a0 += y1s[r0 + 0][k] * wv;
            a1 += y1s[r0 + 1][k] * wv;
        }
        y2s[r0 + 0][j] = fmaxf(a0, 0.f);
        y2s[r0 + 1][j] = fmaxf(a1, 0.f);
    }
    __syncthreads();

    {
        float p = y2s[warp][lane] * wc3[lane] + y2s[warp][lane + 32] * wc3[lane + 32];
        #pragma unroll
        for (int o = 16; o > 0; o >>= 1) p += __shfl_down_sync(0xffffffffu, p, o);
        if (lane == 0) out[rowBase + warp] = p + bc3[0];
    }
}

// ---------------- launch ----------------
extern "C" void kernel_launch(void* const* d_in, const int* in_sizes, int n_in,
                              void* d_out, int out_size)
{
    const void*  indices = d_in[0];
    const int*   src   = (const int*)  d_in[1];
    const int*   dst   = (const int*)  d_in[2];
    const float* w     = (const float*)d_in[3];
    const float* ndata = (const float*)d_in[4];
    const float* W1    = (const float*)d_in[5];
    const float* b1    = (const float*)d_in[6];
    const float* W2    = (const float*)d_in[7];
    const float* b2    = (const float*)d_in[8];
    const float* eps   = (const float*)d_in[9];
    const float* Wc1   = (const float*)d_in[10];
    const float* bc1   = (const float*)d_in[11];
    const float* Wc2   = (const float*)d_in[12];
    const float* bc2   = (const float*)d_in[13];
    const float* Wc3   = (const float*)d_in[14];
    const float* bc3   = (const float*)d_in[15];
    float* out = (float*)d_out;

    (void)in_sizes; (void)n_in; (void)out_size;

    static bool s_attr = false;
    if (!s_attr) {
        cudaFuncSetAttribute(k_gemm, cudaFuncAttributeMaxDynamicSharedMemorySize, SMEM_DYN);
        s_attr = true;
    }

    int nbScan = (NN + 511) / 512;
    int nbGather = (NN * 32 + 255) / 256;   // warp per node

    k_prep <<<616, 256>>>(indices, Wc1, Wc2);
    k_deg  <<<(EE + 255) / 256, 256>>>(dst);
    k_scan1<<<nbScan, 512>>>();
    k_scan3<<<nbScan, 512>>>();
    k_csr  <<<(EE + 255) / 256, 256>>>(src, dst, w);

    k_gather<<<nbGather, 256>>>(ndata, eps, 0);
    k_gemm  <<<NTILES, 256, SMEM_DYN>>>(W1, b1, 0);
    k_gather<<<nbGather, 256>>>(ndata, eps, 1);
    k_gemm  <<<NTILES, 256, SMEM_DYN>>>(W2, b2, 1);

    k_head <<<BB / 8, 256>>>(indices, bc1, bc2, Wc3, bc3, out);
}